// round 7
// baseline (speedup 1.0000x reference)
#include <cuda_runtime.h>
#include <cooperative_groups.h>
#include <math.h>

namespace cg = cooperative_groups;

#define NB 32
#define CD 512
#define PD 1600
#define KC 64
#define EPSF 1e-12f

// ---------------------------------------------------------------------------
// kmain: cluster of 4 CTAs per sample n (one CTA per 16-cluster group kq).
// Per pixel tile (160 px):
//   Phase A: CTA computes scores[16][160] (GEMM over all 512 c, smem-tiled).
//   Cluster exchange: per-pixel max partials, then exp-sum partials (DSMEM).
//   Softmax -> s_soft[16][160]; per-thread mass accumulation.
//   Phase B: agg[16k][512c] += soft * x^T, agg in registers (32 f32/thread).
// Epilogue (fused K3): mass reduce; v = agg - mass*centroid; intra-normalize;
// write final (pre-global-norm) rows to out[n][k][c].
// 256 threads. Phase A map: ka = t&15 (cluster), txa = t>>4 (10-px group).
//              Phase B map: kb = t>>4 (cluster), cg = t&15 (32-c group).
// ---------------------------------------------------------------------------
__global__ __launch_bounds__(256) __cluster_dims__(4, 1, 1)
void kmain(const float* __restrict__ x, const float* __restrict__ conv_w,
           const float* __restrict__ conv_b, const float* __restrict__ centroids,
           float* __restrict__ outp)
{
    __shared__ __align__(16) float s_soft[16 * 164];   // [k][p], pad 164
    __shared__ __align__(16) float s_buf[16 * 516];    // A: x[16][164]+w[16][17]; B: xt[16][516]
    __shared__ float s_red[16 * 17];
    __shared__ float pbuf[160];                        // max partials (DSMEM-read by peers)
    __shared__ float qbuf[160];                        // expsum partials
    __shared__ float gmax[160];
    __shared__ float ginv[160];
    __shared__ float s_mass[16];

    cg::cluster_group cluster = cg::this_cluster();

    const int t   = threadIdx.x;
    const int kq  = blockIdx.x;            // cluster rank (cluster spans x)
    const int n   = blockIdx.y;
    const int kbase = kq * 16;
    const int ka = t & 15, txa = t >> 4;
    const int kb = t >> 4, cgc = t & 15;

    float* s_x = s_buf;                    // [16][164]
    float* s_w = s_buf + 16 * 164;         // [16][17]

    float agg[32];
#pragma unroll
    for (int j = 0; j < 32; j++) agg[j] = 0.f;
    float msum = 0.f;
    const float bias = __ldg(conv_b + kbase + ka);
    const float* xb = x + (size_t)n * CD * PD;

    for (int p0 = 0; p0 < PD; p0 += 160) {
        // ---------- Phase A: scores for 16 clusters x 160 pixels ----------
        float sc[10];
#pragma unroll
        for (int j = 0; j < 10; j++) sc[j] = 0.f;

        for (int c0 = 0; c0 < CD; c0 += 16) {
            __syncthreads();
            {   // W chunk [16k][16c] -> s_w[cc][k]
                int k = t >> 4, cc = t & 15;
                s_w[cc * 17 + k] = conv_w[(size_t)(kbase + k) * CD + c0 + cc];
            }
            {   // x chunk [16c][160p]: 640 float4
#pragma unroll
                for (int it = 0; it < 3; it++) {
                    int idx = t + it * 256;
                    if (idx < 640) {
                        int row = idx / 40, col = (idx % 40) * 4;
                        float4 v = *reinterpret_cast<const float4*>(xb + (size_t)(c0 + row) * PD + p0 + col);
                        *reinterpret_cast<float4*>(&s_x[row * 164 + col]) = v;
                    }
                }
            }
            __syncthreads();
#pragma unroll
            for (int cc = 0; cc < 16; cc++) {
                float a = s_w[cc * 17 + ka];
#pragma unroll
                for (int j = 0; j < 10; j++)
                    sc[j] = fmaf(a, s_x[cc * 164 + txa * 10 + j], sc[j]);
            }
        }
#pragma unroll
        for (int j = 0; j < 10; j++) sc[j] += bias;

        // per-pixel max over this CTA's 16 clusters (16 consecutive lanes = ka)
        float pm[10];
#pragma unroll
        for (int j = 0; j < 10; j++) {
            float v = sc[j];
#pragma unroll
            for (int o = 1; o < 16; o <<= 1)
                v = fmaxf(v, __shfl_xor_sync(0xffffffffu, v, o));
            pm[j] = v;
        }
        __syncthreads();      // prior-tile DSMEM/gmax use complete before rewrite
        if (ka == 0)
#pragma unroll
            for (int j = 0; j < 10; j++) pbuf[txa * 10 + j] = pm[j];
        cluster.sync();       // pbuf visible cluster-wide

        // gather global max across 4 ranks
        if (t < 160) {
            float m = -1e30f;
#pragma unroll
            for (int r = 0; r < 4; r++) {
                const float* rp = cluster.map_shared_rank(pbuf, r);
                m = fmaxf(m, rp[t]);
            }
            gmax[t] = m;
        }
        __syncthreads();

        // exp + per-pixel partial sum over 16 clusters
        float e[10];
#pragma unroll
        for (int j = 0; j < 10; j++) {
            e[j] = __expf(sc[j] - gmax[txa * 10 + j]);
            float v = e[j];
#pragma unroll
            for (int o = 1; o < 16; o <<= 1)
                v += __shfl_xor_sync(0xffffffffu, v, o);
            sc[j] = v;        // reuse: partial sum
        }
        if (ka == 0)
#pragma unroll
            for (int j = 0; j < 10; j++) qbuf[txa * 10 + j] = sc[j];
        cluster.sync();       // qbuf visible; also: all ranks done reading pbuf

        if (t < 160) {
            float s = 0.f;
#pragma unroll
            for (int r = 0; r < 4; r++) {
                const float* rp = cluster.map_shared_rank(qbuf, r);
                s += rp[t];
            }
            ginv[t] = 1.0f / s;
        }
        __syncthreads();

        // softmax weights -> s_soft; accumulate mass
#pragma unroll
        for (int j = 0; j < 10; j++) {
            float w = e[j] * ginv[txa * 10 + j];
            s_soft[ka * 164 + txa * 10 + j] = w;
            msum += w;
        }
        __syncthreads();

        // ---------- Phase B: agg[16k][512c] += soft * x^T ----------
        for (int pt = 0; pt < 160; pt += 16) {
            {   // xt[16p][512c] (pad 516): 8192 words
#pragma unroll
                for (int it = 0; it < 32; it++) {
                    int idx = t + it * 256;
                    int c = idx >> 4, pp = idx & 15;
                    s_buf[pp * 516 + c] = xb[(size_t)c * PD + p0 + pt + pp];
                }
            }
            __syncthreads();
#pragma unroll
            for (int pp = 0; pp < 16; pp++) {
                int ppr = (pp + cgc) & 15;     // stagger: conflict-free f4 reads
                float sv = s_soft[kb * 164 + pt + ppr];
                const float4* xr = reinterpret_cast<const float4*>(&s_buf[ppr * 516 + cgc * 32]);
#pragma unroll
                for (int j = 0; j < 8; j++) {
                    float4 v = xr[j];
                    agg[4 * j + 0] = fmaf(sv, v.x, agg[4 * j + 0]);
                    agg[4 * j + 1] = fmaf(sv, v.y, agg[4 * j + 1]);
                    agg[4 * j + 2] = fmaf(sv, v.z, agg[4 * j + 2]);
                    agg[4 * j + 3] = fmaf(sv, v.w, agg[4 * j + 3]);
                }
            }
            __syncthreads();
        }
    }

    // ---------- fused epilogue: mass, subtract, intra-normalize ----------
    s_red[txa * 17 + ka] = msum;
    __syncthreads();
    if (t < 16) {
        float s = 0.f;
#pragma unroll
        for (int i = 0; i < 16; i++) s += s_red[i * 17 + t];
        s_mass[t] = s;
    }
    __syncthreads();

    const float mass = s_mass[kb];
    const float* cp = centroids + (size_t)(kbase + kb) * CD + cgc * 32;
    float ss = 0.f;
#pragma unroll
    for (int j = 0; j < 8; j++) {
        float4 cv = *reinterpret_cast<const float4*>(cp + 4 * j);
        agg[4 * j + 0] -= mass * cv.x;
        agg[4 * j + 1] -= mass * cv.y;
        agg[4 * j + 2] -= mass * cv.z;
        agg[4 * j + 3] -= mass * cv.w;
#pragma unroll
        for (int q = 0; q < 4; q++) ss += agg[4 * j + q] * agg[4 * j + q];
    }
    // row sumsq: reduce across the 16 cgc lanes of this kb (consecutive lanes)
#pragma unroll
    for (int o = 1; o < 16; o <<= 1) ss += __shfl_xor_sync(0xffffffffu, ss, o);
    const float scale = 1.0f / fmaxf(sqrtf(ss), EPSF);

    float* op = outp + ((size_t)n * KC + kbase + kb) * CD + cgc * 32;
#pragma unroll
    for (int j = 0; j < 8; j++) {
        float4 v = make_float4(agg[4 * j] * scale, agg[4 * j + 1] * scale,
                               agg[4 * j + 2] * scale, agg[4 * j + 3] * scale);
        *reinterpret_cast<float4*>(op + 4 * j) = v;
    }
}

// ---------------------------------------------------------------------------
// kglobal: per-sample global L2 norm, in place. Recomputes row energy from the
// written rows (1 per non-degenerate row, 0 for degenerate) — no scratch.
// One block per n; 256 threads.
// ---------------------------------------------------------------------------
__global__ __launch_bounds__(256) void kglobal(float* __restrict__ outp)
{
    __shared__ float sred[8];
    __shared__ float sg;
    const int t = threadIdx.x;
    const int n = blockIdx.x;

    float4* ob = reinterpret_cast<float4*>(outp + (size_t)n * (KC * CD));

    float ss = 0.f;
#pragma unroll
    for (int it = 0; it < 32; it++) {              // 32*256 float4 = 32768 floats
        float4 v = ob[t + it * 256];
        ss += v.x * v.x + v.y * v.y + v.z * v.z + v.w * v.w;
    }
#pragma unroll
    for (int o = 16; o > 0; o >>= 1) ss += __shfl_xor_sync(0xffffffffu, ss, o);
    if ((t & 31) == 0) sred[t >> 5] = ss;
    __syncthreads();
    if (t == 0) {
        float tot = 0.f;
#pragma unroll
        for (int i = 0; i < 8; i++) tot += sred[i];
        sg = 1.0f / fmaxf(sqrtf(tot), EPSF);
    }
    __syncthreads();
    const float scale = sg;

#pragma unroll
    for (int it = 0; it < 32; it++) {
        float4 v = ob[t + it * 256];
        v.x *= scale; v.y *= scale; v.z *= scale; v.w *= scale;
        ob[t + it * 256] = v;
    }
}

// ---------------------------------------------------------------------------
extern "C" void kernel_launch(void* const* d_in, const int* in_sizes, int n_in,
                              void* d_out, int out_size)
{
    const float* x         = (const float*)d_in[0];
    const float* centroids = (const float*)d_in[1];
    const float* conv_w    = (const float*)d_in[2];
    const float* conv_b    = (const float*)d_in[3];
    float* out = (float*)d_out;

    kmain<<<dim3(4, NB), 256>>>(x, conv_w, conv_b, centroids, out);
    kglobal<<<NB, 256>>>(out);
}

// round 8
// speedup vs baseline: 1.0070x; 1.0070x over previous
#include <cuda_runtime.h>
#include <cooperative_groups.h>
#include <math.h>

namespace cg = cooperative_groups;

#define NB 32
#define CD 512
#define PD 1600
#define KC 64
#define EPSF 1e-12f

// ---------------------------------------------------------------------------
// kmain: cluster of 4 CTAs per sample n (one CTA per 16-cluster group kq).
// Per pixel tile (160 px):
//   Phase A: CTA computes scores[16][160] (GEMM over all 512 c, smem-tiled).
//   Cluster exchange: per-pixel max partials, then exp-sum partials (DSMEM).
//   Softmax -> s_soft[16][160]; per-thread mass accumulation.
//   Phase B: agg[16k][512c] += soft * x^T, agg in registers (32 f32/thread).
// Epilogue (fused K3): mass reduce; v = agg - mass*centroid; intra-normalize;
// write final (pre-global-norm) rows to out[n][k][c].
// 256 threads. Phase A map: ka = t&15 (cluster), txa = t>>4 (10-px group).
//              Phase B map: kb = t>>4 (cluster), cg = t&15 (32-c group).
// ---------------------------------------------------------------------------
__global__ __launch_bounds__(256) __cluster_dims__(4, 1, 1)
void kmain(const float* __restrict__ x, const float* __restrict__ conv_w,
           const float* __restrict__ conv_b, const float* __restrict__ centroids,
           float* __restrict__ outp)
{
    __shared__ __align__(16) float s_soft[16 * 164];   // [k][p], pad 164
    __shared__ __align__(16) float s_buf[16 * 516];    // A: x[16][164]+w[16][17]; B: xt[16][516]
    __shared__ float s_red[16 * 17];
    __shared__ float pbuf[160];                        // max partials (DSMEM-read by peers)
    __shared__ float qbuf[160];                        // expsum partials
    __shared__ float gmax[160];
    __shared__ float ginv[160];
    __shared__ float s_mass[16];

    cg::cluster_group cluster = cg::this_cluster();

    const int t   = threadIdx.x;
    const int kq  = blockIdx.x;            // cluster rank (cluster spans x)
    const int n   = blockIdx.y;
    const int kbase = kq * 16;
    const int ka = t & 15, txa = t >> 4;
    const int kb = t >> 4, cgc = t & 15;

    float* s_x = s_buf;                    // [16][164]
    float* s_w = s_buf + 16 * 164;         // [16][17]

    float agg[32];
#pragma unroll
    for (int j = 0; j < 32; j++) agg[j] = 0.f;
    float msum = 0.f;
    const float bias = __ldg(conv_b + kbase + ka);
    const float* xb = x + (size_t)n * CD * PD;

    for (int p0 = 0; p0 < PD; p0 += 160) {
        // ---------- Phase A: scores for 16 clusters x 160 pixels ----------
        float sc[10];
#pragma unroll
        for (int j = 0; j < 10; j++) sc[j] = 0.f;

        for (int c0 = 0; c0 < CD; c0 += 16) {
            __syncthreads();
            {   // W chunk [16k][16c] -> s_w[cc][k]
                int k = t >> 4, cc = t & 15;
                s_w[cc * 17 + k] = conv_w[(size_t)(kbase + k) * CD + c0 + cc];
            }
            {   // x chunk [16c][160p]: 640 float4
#pragma unroll
                for (int it = 0; it < 3; it++) {
                    int idx = t + it * 256;
                    if (idx < 640) {
                        int row = idx / 40, col = (idx % 40) * 4;
                        float4 v = *reinterpret_cast<const float4*>(xb + (size_t)(c0 + row) * PD + p0 + col);
                        *reinterpret_cast<float4*>(&s_x[row * 164 + col]) = v;
                    }
                }
            }
            __syncthreads();
#pragma unroll
            for (int cc = 0; cc < 16; cc++) {
                float a = s_w[cc * 17 + ka];
#pragma unroll
                for (int j = 0; j < 10; j++)
                    sc[j] = fmaf(a, s_x[cc * 164 + txa * 10 + j], sc[j]);
            }
        }
#pragma unroll
        for (int j = 0; j < 10; j++) sc[j] += bias;

        // per-pixel max over this CTA's 16 clusters (16 consecutive lanes = ka)
        float pm[10];
#pragma unroll
        for (int j = 0; j < 10; j++) {
            float v = sc[j];
#pragma unroll
            for (int o = 1; o < 16; o <<= 1)
                v = fmaxf(v, __shfl_xor_sync(0xffffffffu, v, o));
            pm[j] = v;
        }
        __syncthreads();      // prior-tile DSMEM/gmax use complete before rewrite
        if (ka == 0)
#pragma unroll
            for (int j = 0; j < 10; j++) pbuf[txa * 10 + j] = pm[j];
        cluster.sync();       // pbuf visible cluster-wide

        // gather global max across 4 ranks
        if (t < 160) {
            float m = -1e30f;
#pragma unroll
            for (int r = 0; r < 4; r++) {
                const float* rp = cluster.map_shared_rank(pbuf, r);
                m = fmaxf(m, rp[t]);
            }
            gmax[t] = m;
        }
        __syncthreads();

        // exp + per-pixel partial sum over 16 clusters
        float e[10];
#pragma unroll
        for (int j = 0; j < 10; j++) {
            e[j] = __expf(sc[j] - gmax[txa * 10 + j]);
            float v = e[j];
#pragma unroll
            for (int o = 1; o < 16; o <<= 1)
                v += __shfl_xor_sync(0xffffffffu, v, o);
            sc[j] = v;        // reuse: partial sum
        }
        if (ka == 0)
#pragma unroll
            for (int j = 0; j < 10; j++) qbuf[txa * 10 + j] = sc[j];
        cluster.sync();       // qbuf visible; also: all ranks done reading pbuf

        if (t < 160) {
            float s = 0.f;
#pragma unroll
            for (int r = 0; r < 4; r++) {
                const float* rp = cluster.map_shared_rank(qbuf, r);
                s += rp[t];
            }
            ginv[t] = 1.0f / s;
        }
        __syncthreads();

        // softmax weights -> s_soft; accumulate mass
#pragma unroll
        for (int j = 0; j < 10; j++) {
            float w = e[j] * ginv[txa * 10 + j];
            s_soft[ka * 164 + txa * 10 + j] = w;
            msum += w;
        }
        __syncthreads();

        // ---------- Phase B: agg[16k][512c] += soft * x^T ----------
        for (int pt = 0; pt < 160; pt += 16) {
            {   // xt[16p][512c] (pad 516): 8192 words
#pragma unroll
                for (int it = 0; it < 32; it++) {
                    int idx = t + it * 256;
                    int c = idx >> 4, pp = idx & 15;
                    s_buf[pp * 516 + c] = xb[(size_t)c * PD + p0 + pt + pp];
                }
            }
            __syncthreads();
#pragma unroll
            for (int pp = 0; pp < 16; pp++) {
                int ppr = (pp + cgc) & 15;     // stagger: conflict-free f4 reads
                float sv = s_soft[kb * 164 + pt + ppr];
                const float4* xr = reinterpret_cast<const float4*>(&s_buf[ppr * 516 + cgc * 32]);
#pragma unroll
                for (int j = 0; j < 8; j++) {
                    float4 v = xr[j];
                    agg[4 * j + 0] = fmaf(sv, v.x, agg[4 * j + 0]);
                    agg[4 * j + 1] = fmaf(sv, v.y, agg[4 * j + 1]);
                    agg[4 * j + 2] = fmaf(sv, v.z, agg[4 * j + 2]);
                    agg[4 * j + 3] = fmaf(sv, v.w, agg[4 * j + 3]);
                }
            }
            __syncthreads();
        }
    }

    // ---------- fused epilogue: mass, subtract, intra-normalize ----------
    s_red[txa * 17 + ka] = msum;
    __syncthreads();
    if (t < 16) {
        float s = 0.f;
#pragma unroll
        for (int i = 0; i < 16; i++) s += s_red[i * 17 + t];
        s_mass[t] = s;
    }
    __syncthreads();

    const float mass = s_mass[kb];
    const float* cp = centroids + (size_t)(kbase + kb) * CD + cgc * 32;
    float ss = 0.f;
#pragma unroll
    for (int j = 0; j < 8; j++) {
        float4 cv = *reinterpret_cast<const float4*>(cp + 4 * j);
        agg[4 * j + 0] -= mass * cv.x;
        agg[4 * j + 1] -= mass * cv.y;
        agg[4 * j + 2] -= mass * cv.z;
        agg[4 * j + 3] -= mass * cv.w;
#pragma unroll
        for (int q = 0; q < 4; q++) ss += agg[4 * j + q] * agg[4 * j + q];
    }
    // row sumsq: reduce across the 16 cgc lanes of this kb (consecutive lanes)
#pragma unroll
    for (int o = 1; o < 16; o <<= 1) ss += __shfl_xor_sync(0xffffffffu, ss, o);
    const float scale = 1.0f / fmaxf(sqrtf(ss), EPSF);

    float* op = outp + ((size_t)n * KC + kbase + kb) * CD + cgc * 32;
#pragma unroll
    for (int j = 0; j < 8; j++) {
        float4 v = make_float4(agg[4 * j] * scale, agg[4 * j + 1] * scale,
                               agg[4 * j + 2] * scale, agg[4 * j + 3] * scale);
        *reinterpret_cast<float4*>(op + 4 * j) = v;
    }
}

// ---------------------------------------------------------------------------
// kglobal: per-sample global L2 norm, in place. Recomputes row energy from the
// written rows (1 per non-degenerate row, 0 for degenerate) — no scratch.
// One block per n; 256 threads.
// ---------------------------------------------------------------------------
__global__ __launch_bounds__(256) void kglobal(float* __restrict__ outp)
{
    __shared__ float sred[8];
    __shared__ float sg;
    const int t = threadIdx.x;
    const int n = blockIdx.x;

    float4* ob = reinterpret_cast<float4*>(outp + (size_t)n * (KC * CD));

    float ss = 0.f;
#pragma unroll
    for (int it = 0; it < 32; it++) {              // 32*256 float4 = 32768 floats
        float4 v = ob[t + it * 256];
        ss += v.x * v.x + v.y * v.y + v.z * v.z + v.w * v.w;
    }
#pragma unroll
    for (int o = 16; o > 0; o >>= 1) ss += __shfl_xor_sync(0xffffffffu, ss, o);
    if ((t & 31) == 0) sred[t >> 5] = ss;
    __syncthreads();
    if (t == 0) {
        float tot = 0.f;
#pragma unroll
        for (int i = 0; i < 8; i++) tot += sred[i];
        sg = 1.0f / fmaxf(sqrtf(tot), EPSF);
    }
    __syncthreads();
    const float scale = sg;

#pragma unroll
    for (int it = 0; it < 32; it++) {
        float4 v = ob[t + it * 256];
        v.x *= scale; v.y *= scale; v.z *= scale; v.w *= scale;
        ob[t + it * 256] = v;
    }
}

// ---------------------------------------------------------------------------
extern "C" void kernel_launch(void* const* d_in, const int* in_sizes, int n_in,
                              void* d_out, int out_size)
{
    const float* x         = (const float*)d_in[0];
    const float* centroids = (const float*)d_in[1];
    const float* conv_w    = (const float*)d_in[2];
    const float* conv_b    = (const float*)d_in[3];
    float* out = (float*)d_out;

    kmain<<<dim3(4, NB), 256>>>(x, conv_w, conv_b, centroids, out);
    kglobal<<<NB, 256>>>(out);
}

// round 9
// speedup vs baseline: 2.6202x; 2.6019x over previous
#include <cuda_runtime.h>
#include <cooperative_groups.h>
#include <math.h>
namespace cg = cooperative_groups;

#define NB 32
#define CD 512
#define PD 1600
#define KC 64
#define EPSF 1e-12f
#define TILE 32
#define NT 50
#define XP 34

// shared memory layout (float offsets)
#define OXT0 0            // x tile buf0 [512][34]
#define OXT1 17408        // x tile buf1
#define OWT  34816        // W^T [512][18]
#define OPS  44032        // partial scores [8w][512] (swizzled pairs)
#define OSC  48128        // scoreT/softT [16][34]
#define OGM  48672        // gmax[32]
#define OGI  48704        // ginv[32]
#define OPB  48736        // cluster max partials / final scales [32]
#define OQB  48768        // cluster sum partials [32]
#define OBI  48800        // bias[16]
#define OMS  48816        // mass[16]
#define OSS  48832        // ss partials [32]
#define SMF  48864
#define SMB  (SMF * 4)

typedef unsigned long long ull;
__device__ __forceinline__ ull pk2(float v){ ull r; asm("mov.b64 %0,{%1,%1};":"=l"(r):"f"(v)); return r; }
__device__ __forceinline__ float2 up2(ull v){ float a,b; asm("mov.b64 {%0,%1},%2;":"=f"(a),"=f"(b):"l"(v)); return make_float2(a,b); }
__device__ __forceinline__ void fma2(ull&d, ull a, ull b){ asm("fma.rn.f32x2 %0,%1,%2,%0;":"+l"(d):"l"(a),"l"(b)); }
__device__ __forceinline__ void cpa8(unsigned dst, const float* src){
    asm volatile("cp.async.ca.shared.global [%0],[%1],8;"::"r"(dst),"l"(src));
}

// ---------------------------------------------------------------------------
// kmain: cluster of 4 CTAs per sample (rank = 16-cluster group), 256 threads.
// Per 32-px tile (x tile loaded ONCE, double-buffered via cp.async):
//   Phase A: warp-private c-slices (8 warps x 64c), thread 2k x 8p f32x2 ->
//            partial scores; smem reduce + bias -> scoreT.
//   Softmax: DSMEM max/sum exchange across 4 ranks (exact, deterministic).
//   Phase B: agg[k][c] += soft*x from the SAME x tile; thread 4k x 8c,
//            f32x2 along pixel pairs; acc in registers across all tiles.
// Epilogue: mass, subtract mass*centroid, intra-normalize, store.
// ---------------------------------------------------------------------------
__global__ __launch_bounds__(256) __cluster_dims__(4,1,1)
void kmain(const float* __restrict__ x, const float* __restrict__ conv_w,
           const float* __restrict__ conv_b, const float* __restrict__ cent,
           float* __restrict__ outp)
{
    extern __shared__ float sm[];
    cg::cluster_group cl = cg::this_cluster();
    const int t = threadIdx.x, w = t>>5, lane = t&31;
    const int kq = blockIdx.x, n = blockIdx.y, kbase = kq*16;
    const int kgA = lane>>2, pgA = lane&3;    // A: k-pair 2kgA, p-octet 8pgA
    const int krd = t>>4, prd = t&15;         // reduce/softmax slot (k, p-pair)
    const int kgB = (t>>6)<<2, cgB = t&63;    // B: k = kgB+i, c = cgB+64j
    const float* xb = x + (size_t)n*CD*PD;
    unsigned smb = (unsigned)__cvta_generic_to_shared(sm);

    // stage W^T (once) and bias
    for (int i = 0; i < 32; i++) {
        int g = i*256 + t, k = g>>9, c = g&511;
        sm[OWT + c*18 + k] = conv_w[(size_t)(kbase+k)*CD + c];
    }
    if (t < 16) sm[OBI+t] = conv_b[kbase+t];

    ull acc2[4][8];
#pragma unroll
    for (int i=0;i<4;i++)
#pragma unroll
        for (int j=0;j<8;j++) acc2[i][j]=0ULL;
    float msum = 0.f;

    // prologue: tile 0 -> buf0
    for (int i=0;i<32;i++){ int idx=t+256*i, r=idx>>4, o=(idx&15)*2;
        cpa8(smb + (unsigned)(OXT0 + r*XP + o)*4u, xb + (size_t)r*PD + o); }
    asm volatile("cp.async.commit_group;");

    for (int tile=0; tile<NT; tile++){
        float* cur = sm + ((tile&1)? OXT1:OXT0);
        if (tile+1 < NT){
            int bo = ((tile+1)&1)? OXT1:OXT0;
            int pn = (tile+1)*TILE;
            for (int i=0;i<32;i++){ int idx=t+256*i, r=idx>>4, o=(idx&15)*2;
                cpa8(smb + (unsigned)(bo + r*XP + o)*4u, xb + (size_t)r*PD + pn + o); }
            asm volatile("cp.async.commit_group;");
            asm volatile("cp.async.wait_group 1;");
        } else {
            asm volatile("cp.async.wait_group 0;");
        }
        __syncthreads();

        // ---- Phase A: per-warp c-slice partial scores ----
        ull pa[2][4];
#pragma unroll
        for (int i=0;i<2;i++)
#pragma unroll
            for (int u=0;u<4;u++) pa[i][u]=0ULL;
        {
            const float* xw = cur + w*64*XP + pgA*8;
            const float* wp = sm + OWT + w*64*18 + kgA*2;
#pragma unroll 4
            for (int cc=0; cc<64; cc++){
                float2 wv = *(const float2*)wp;
                ull w0 = pk2(wv.x), w1 = pk2(wv.y);
#pragma unroll
                for (int u=0;u<4;u++){
                    ull xv = *(const ull*)(xw + 2*u);
                    fma2(pa[0][u], w0, xv);
                    fma2(pa[1][u], w1, xv);
                }
                xw += XP; wp += 18;
            }
        }
#pragma unroll
        for (int i=0;i<2;i++){
            int k = kgA*2 + i;
#pragma unroll
            for (int u=0;u<4;u++){
                int pp = pgA*4 + u;
                *(float2*)(sm + OPS + w*512 + k*32 + ((pp + k)&15)*2) = up2(pa[i][u]);
            }
        }
        __syncthreads();

        // ---- reduce partials + bias -> scoreT ----
        float s0, s1;
        {
            float2 a = make_float2(0.f, 0.f);
            int base = OPS + krd*32 + ((prd + krd)&15)*2;
#pragma unroll
            for (int wv=0; wv<8; wv++){
                float2 pv = *(const float2*)(sm + base + wv*512);
                a.x += pv.x; a.y += pv.y;
            }
            float b = sm[OBI + krd];
            s0 = a.x + b; s1 = a.y + b;
            *(float2*)(sm + OSC + krd*XP + prd*2) = make_float2(s0, s1);
        }
        __syncthreads();

        // ---- softmax via cluster exchange ----
        if (t < TILE){
            float m = -1e30f;
#pragma unroll
            for (int k=0;k<16;k++) m = fmaxf(m, sm[OSC + k*XP + t]);
            sm[OPB + t] = m;
        }
        cl.sync();
        if (t < TILE){
            float m = -1e30f;
#pragma unroll
            for (int r=0;r<4;r++) m = fmaxf(m, cl.map_shared_rank(sm + OPB, r)[t]);
            sm[OGM + t] = m;
        }
        __syncthreads();
        float e0, e1;
        {
            float2 g = *(const float2*)(sm + OGM + prd*2);
            e0 = __expf(s0 - g.x); e1 = __expf(s1 - g.y);
            *(float2*)(sm + OSC + krd*XP + prd*2) = make_float2(e0, e1);
        }
        __syncthreads();
        if (t < TILE){
            float s = 0.f;
#pragma unroll
            for (int k=0;k<16;k++) s += sm[OSC + k*XP + t];
            sm[OQB + t] = s;
        }
        cl.sync();
        if (t < TILE){
            float s = 0.f;
#pragma unroll
            for (int r=0;r<4;r++) s += cl.map_shared_rank(sm + OQB, r)[t];
            sm[OGI + t] = 1.0f/s;
        }
        __syncthreads();
        {
            float2 g = *(const float2*)(sm + OGI + prd*2);
            float w0 = e0*g.x, w1 = e1*g.y;
            *(float2*)(sm + OSC + krd*XP + prd*2) = make_float2(w0, w1);
            msum += w0 + w1;
        }
        __syncthreads();

        // ---- Phase B: agg += soft * x (same tile, no transpose) ----
        {
            const float* xc = cur + cgB*XP;
            const float* sp = sm + OSC + kgB*XP;
#pragma unroll
            for (int pp=0; pp<16; pp++){
                ull sv[4], xv[8];
#pragma unroll
                for (int i=0;i<4;i++) sv[i] = *(const ull*)(sp + i*XP + 2*pp);
#pragma unroll
                for (int j=0;j<8;j++) xv[j] = *(const ull*)(xc + j*64*XP + 2*pp);
#pragma unroll
                for (int i=0;i<4;i++)
#pragma unroll
                    for (int j=0;j<8;j++) fma2(acc2[i][j], sv[i], xv[j]);
            }
        }
        __syncthreads();   // cur buffer reused by cp.async in 2 tiles
    }

    // ---- epilogue: mass, subtract, intra-normalize, store ----
#pragma unroll
    for (int o=1;o<16;o<<=1) msum += __shfl_xor_sync(0xffffffffu, msum, o);
    if (prd == 0) sm[OMS + krd] = msum;
    __syncthreads();

    float v[4][8], ssk[4];
#pragma unroll
    for (int i=0;i<4;i++){
        float mass = sm[OMS + kgB + i];
        const float* cp = cent + (size_t)(kbase + kgB + i)*CD + cgB;
        ssk[i] = 0.f;
#pragma unroll
        for (int j=0;j<8;j++){
            float2 a = up2(acc2[i][j]);
            float val = a.x + a.y - mass*cp[j*64];
            v[i][j] = val; ssk[i] += val*val;
        }
    }
#pragma unroll
    for (int i=0;i<4;i++){
        float s = ssk[i];
#pragma unroll
        for (int o=1;o<32;o<<=1) s += __shfl_xor_sync(0xffffffffu, s, o);
        if (lane == 0) sm[OSS + (t>>6)*8 + (w&1)*4 + i] = s;
    }
    __syncthreads();
    if (t < 16){
        float s = sm[OSS + (t>>2)*8 + (t&3)] + sm[OSS + (t>>2)*8 + 4 + (t&3)];
        sm[OPB + t] = 1.0f / fmaxf(sqrtf(s), EPSF);
    }
    __syncthreads();
#pragma unroll
    for (int i=0;i<4;i++){
        float sc = sm[OPB + kgB + i];
        float* op = outp + ((size_t)n*KC + kbase + kgB + i)*CD + cgB;
#pragma unroll
        for (int j=0;j<8;j++) op[j*64] = v[i][j]*sc;
    }
}

// ---------------------------------------------------------------------------
// kglobal: per-sample global L2 norm, in place (recomputes row energy; rows
// are unit-norm or exactly zero, so this equals the reference's global norm).
// ---------------------------------------------------------------------------
__global__ __launch_bounds__(512) void kglobal(float* __restrict__ outp)
{
    __shared__ float sred[16];
    __shared__ float sg;
    const int t = threadIdx.x, n = blockIdx.x;
    float4* ob = reinterpret_cast<float4*>(outp + (size_t)n*KC*CD);

    float ss = 0.f;
#pragma unroll
    for (int i=0;i<16;i++){
        float4 u = ob[t + i*512];
        ss += u.x*u.x + u.y*u.y + u.z*u.z + u.w*u.w;
    }
#pragma unroll
    for (int o=16;o>0;o>>=1) ss += __shfl_xor_sync(0xffffffffu, ss, o);
    if ((t&31) == 0) sred[t>>5] = ss;
    __syncthreads();
    if (t == 0){
        float tot = 0.f;
#pragma unroll
        for (int i=0;i<16;i++) tot += sred[i];
        sg = 1.0f / fmaxf(sqrtf(tot), EPSF);
    }
    __syncthreads();
    const float sc = sg;
#pragma unroll
    for (int i=0;i<16;i++){
        float4 u = ob[t + i*512];
        u.x *= sc; u.y *= sc; u.z *= sc; u.w *= sc;
        ob[t + i*512] = u;
    }
}

// ---------------------------------------------------------------------------
extern "C" void kernel_launch(void* const* d_in, const int* in_sizes, int n_in,
                              void* d_out, int out_size)
{
    const float* x         = (const float*)d_in[0];
    const float* centroids = (const float*)d_in[1];
    const float* conv_w    = (const float*)d_in[2];
    const float* conv_b    = (const float*)d_in[3];
    float* out = (float*)d_out;

    cudaFuncSetAttribute(kmain, cudaFuncAttributeMaxDynamicSharedMemorySize, SMB);
    kmain<<<dim3(4, NB), 256, SMB>>>(x, conv_w, conv_b, centroids, out);
    kglobal<<<NB, 512>>>(out);
}